// round 14
// baseline (speedup 1.0000x reference)
#include <cuda_runtime.h>
#include <math.h>

// ---------------- problem constants (fixed by setup_inputs) ----------------
namespace pr {
constexpr int B  = 64;
constexpr int P  = 576;
constexpr int D  = 768;
constexpr int NG = 64;
constexpr int NN = 65;      // GROUPS + 1
constexpr int STEPS = 8;
constexpr float FLOORV = 1e-4f;
constexpr float EPSV   = 1e-4f;
constexpr float DTV    = 0.1f;
constexpr float GAMMAV = 0.1f;
constexpr int   KEEPC  = 288;   // round(576 * 0.5)

// output tuple layout (flattened, float32):
// keep_mask(B,577), patch_keep_mask(B,576), gid(B,576), group_scores(B,576),
// d_hist(B,9,65,65), q_hist(B,8,65,65), routing(B,64,64), aux_sparse, aux_stable
constexpr int OFF_KEEP   = 0;
constexpr int OFF_PATCH  = OFF_KEEP  + B * (P + 1);
constexpr int OFF_GID    = OFF_PATCH + B * P;
constexpr int OFF_GSC    = OFF_GID   + B * P;
constexpr int OFF_DH     = OFF_GSC   + B * P;
constexpr int OFF_QH     = OFF_DH    + B * 9 * NN * NN;
constexpr int OFF_ROUT   = OFF_QH    + B * 8 * NN * NN;
constexpr int OFF_SPARSE = OFF_ROUT  + B * NG * NG;
constexpr int OFF_STABLE = OFF_SPARSE + 1;
}

// ---------------- scratch (__device__ globals; no allocation) ----------------
__device__ float g_nodes[pr::B * pr::NN * pr::D];   // (B,65,768)
__device__ float g_proj [pr::B * pr::NN * pr::D];   // (B,65,768) normalized
__device__ float g_gf   [pr::B * pr::NG];           // group_flow
__device__ float g_aux_sp[pr::B];
__device__ float g_aux_st[pr::B];

// ======================================================================
// K1: group means + nodes assembly.  grid = B*65 blocks, 256 threads.
// ======================================================================
__global__ void k_groups(const float* __restrict__ tokens,
                         const float* __restrict__ cls,
                         const int* gh_p, const int* gw_p) {
    const int b = blockIdx.x / pr::NN;
    const int n = blockIdx.x % pr::NN;
    float* dst = g_nodes + ((size_t)b * pr::NN + n) * pr::D;

    if (n == 0) {
        for (int d = threadIdx.x; d < pr::D; d += blockDim.x)
            dst[d] = cls[(size_t)b * pr::D + d];
        return;
    }
    const int GH = gh_p ? *gh_p : 24;
    const int GW = gw_p ? *gw_p : 24;
    const int g  = n - 1;
    const int gh = (GH + 7) / 8;
    const int gw = (GW + 7) / 8;
    const int gr = g / 8, gc = g % 8;
    int r0 = gr * gh;  int r1 = (gr == 7) ? GH : min((gr + 1) * gh, GH);
    int c0 = gc * gw;  int c1 = (gc == 7) ? GW : min((gc + 1) * gw, GW);
    if (r0 > GH) r0 = GH;
    if (c0 > GW) c0 = GW;
    const int cnt = (r1 > r0 && c1 > c0) ? (r1 - r0) * (c1 - c0) : 0;
    const float inv = 1.0f / (float)max(cnt, 1);

    for (int d = threadIdx.x; d < pr::D; d += blockDim.x) {
        float acc = 0.0f;
        for (int r = r0; r < r1; r++)
            for (int c = c0; c < c1; c++)
                acc += tokens[((size_t)b * pr::P + r * GW + c) * pr::D + d];
        dst[d] = acc * inv;
    }
}

// ======================================================================
// K2: proj = nodes @ W^T   (M=4160, N=768, K=768, fp32, NT layout)
// 128x64 block tile, 16 K-slice, 256 threads, 8x4 micro tile.
// ======================================================================
__global__ void __launch_bounds__(256) k_gemm(const float* __restrict__ W) {
    __shared__ float As[16][128 + 4];
    __shared__ float Bs[16][64 + 4];
    const int M = pr::B * pr::NN;                 // 4160
    const int m0 = blockIdx.y * 128;
    const int n0 = blockIdx.x * 64;
    const int tid = threadIdx.x;
    const int tx = tid & 15, ty = tid >> 4;       // 16 x 16 thread grid
    const int lr = tid >> 2, lc = tid & 3;        // loader layout

    float acc[8][4];
#pragma unroll
    for (int i = 0; i < 8; i++)
#pragma unroll
        for (int j = 0; j < 4; j++) acc[i][j] = 0.0f;

    const float* A = g_nodes;
    for (int k0 = 0; k0 < pr::D; k0 += 16) {
#pragma unroll
        for (int h = 0; h < 2; h++) {
            const int m = m0 + lr + h * 64;
            float4 v = make_float4(0.f, 0.f, 0.f, 0.f);
            if (m < M) v = *(const float4*)(A + (size_t)m * pr::D + k0 + lc * 4);
            As[lc * 4 + 0][lr + h * 64] = v.x;
            As[lc * 4 + 1][lr + h * 64] = v.y;
            As[lc * 4 + 2][lr + h * 64] = v.z;
            As[lc * 4 + 3][lr + h * 64] = v.w;
        }
        {
            const float4 v = *(const float4*)(W + (size_t)(n0 + lr) * pr::D + k0 + lc * 4);
            Bs[lc * 4 + 0][lr] = v.x;
            Bs[lc * 4 + 1][lr] = v.y;
            Bs[lc * 4 + 2][lr] = v.z;
            Bs[lc * 4 + 3][lr] = v.w;
        }
        __syncthreads();
#pragma unroll
        for (int kk = 0; kk < 16; kk++) {
            float a[8], bv[4];
#pragma unroll
            for (int i = 0; i < 8; i++) a[i] = As[kk][ty * 8 + i];
#pragma unroll
            for (int j = 0; j < 4; j++) bv[j] = Bs[kk][tx * 4 + j];
#pragma unroll
            for (int i = 0; i < 8; i++)
#pragma unroll
                for (int j = 0; j < 4; j++) acc[i][j] += a[i] * bv[j];
        }
        __syncthreads();
    }
#pragma unroll
    for (int i = 0; i < 8; i++) {
        const int m = m0 + ty * 8 + i;
        if (m < M) {
            float4 v = make_float4(acc[i][0], acc[i][1], acc[i][2], acc[i][3]);
            *(float4*)(g_proj + (size_t)m * pr::D + n0 + tx * 4) = v;
        }
    }
}

// ======================================================================
// K2b: row normalization of proj (in place). grid = 4160, 256 threads.
// ======================================================================
__global__ void k_rownorm() {
    float* pr_row = g_proj + (size_t)blockIdx.x * pr::D;
    __shared__ float red[256];
    float s = 0.0f;
    for (int d = threadIdx.x; d < pr::D; d += 256) {
        const float v = pr_row[d];
        s += v * v;
    }
    red[threadIdx.x] = s;
    __syncthreads();
    for (int o = 128; o > 0; o >>= 1) {
        if (threadIdx.x < o) red[threadIdx.x] += red[threadIdx.x + o];
        __syncthreads();
    }
    const float scale = 1.0f / fmaxf(sqrtf(red[0]), 1e-12f);
    for (int d = threadIdx.x; d < pr::D; d += 256) pr_row[d] *= scale;
}

// ======================================================================
// K3: per-batch 65x65 Gram + initial C -> d_hist[b,0].  grid = B blocks.
// 4x4 register tiles over i<=j triangle, reads L2-resident proj.
// ======================================================================
__global__ void __launch_bounds__(256) k_gram(float* __restrict__ out) {
    __shared__ float Gs[pr::NN][pr::NN + 1];
    const int b = blockIdx.x;
    const float* __restrict__ Pb = g_proj + (size_t)b * pr::NN * pr::D;
    const int t = threadIdx.x;

    if (t < 153) {                       // 17*18/2 upper-triangle 4x4 tiles
        int ti = 0, rem = t;
        while (rem >= 17 - ti) { rem -= 17 - ti; ti++; }
        const int tj = ti + rem;
        const int i0 = ti * 4, j0 = tj * 4;
        float acc[4][4];
#pragma unroll
        for (int u = 0; u < 4; u++)
#pragma unroll
            for (int v = 0; v < 4; v++) acc[u][v] = 0.0f;

        for (int k = 0; k < pr::D; k += 4) {
            float4 a[4], bb[4];
#pragma unroll
            for (int u = 0; u < 4; u++) {
                const int ii = min(i0 + u, pr::NN - 1);
                const int jj = min(j0 + u, pr::NN - 1);
                a[u]  = *(const float4*)(Pb + (size_t)ii * pr::D + k);
                bb[u] = *(const float4*)(Pb + (size_t)jj * pr::D + k);
            }
#pragma unroll
            for (int u = 0; u < 4; u++)
#pragma unroll
                for (int v = 0; v < 4; v++)
                    acc[u][v] += a[u].x * bb[v].x + a[u].y * bb[v].y +
                                 a[u].z * bb[v].z + a[u].w * bb[v].w;
        }
#pragma unroll
        for (int u = 0; u < 4; u++)
#pragma unroll
            for (int v = 0; v < 4; v++) {
                const int i = i0 + u, j = j0 + v;
                if (i < pr::NN && j < pr::NN) {
                    Gs[i][j] = acc[u][v];
                    Gs[j][i] = acc[u][v];
                }
            }
    }
    __syncthreads();

    float* dh0 = out + pr::OFF_DH + (size_t)b * 9 * pr::NN * pr::NN;
    for (int idx = t; idx < pr::NN * pr::NN; idx += blockDim.x) {
        const int i = idx / pr::NN, j = idx % pr::NN;
        const float d2 = fmaxf(Gs[i][i] + Gs[j][j] - 2.0f * Gs[i][j], 0.0f);
        dh0[idx] = (i == j) ? 0.0f : fmaxf(expf(-d2), pr::FLOORV);
    }
}

// ======================================================================
// K4: Physarum dynamics. One block per batch, 512 threads.
// 8 steps of: degree, diagonally-dominant 65x65 Gauss-Jordan solve, flow,
// conductance update. Writes d_hist/q_hist/routing directly to d_out.
// ======================================================================
__global__ void __launch_bounds__(512) k_dyn(float* __restrict__ out) {
    __shared__ float Cs[pr::NN][66];
    __shared__ float Sys[pr::NN][72];      // 66 used; stride 72 -> conflict-free GJ
    __shared__ float pvec[pr::NN];
    __shared__ float degs[pr::NN];
    __shared__ float red[512];

    const int b = blockIdx.x;
    const int tid = threadIdx.x;
    float* dh = out + pr::OFF_DH + (size_t)b * 9 * pr::NN * pr::NN;
    float* qh = out + pr::OFF_QH + (size_t)b * 8 * pr::NN * pr::NN;

    for (int idx = tid; idx < pr::NN * pr::NN; idx += 512)
        Cs[idx / pr::NN][idx % pr::NN] = dh[idx];
    __syncthreads();

    float stable_acc = 0.0f;
    const int rslot = tid >> 3;     // 0..63
    const int jlane = tid & 7;

    for (int t = 0; t < pr::STEPS; t++) {
        if (tid < pr::NN) {
            float s = 0.0f;
            for (int j = 0; j < pr::NN; j++) s += Cs[tid][j];
            degs[tid] = s;
        }
        __syncthreads();
        for (int idx = tid; idx < pr::NN * 66; idx += 512) {
            const int i = idx / 66, j = idx % 66;
            float v;
            if (j == 65)      v = (i == 0) ? 1.0f : (-1.0f / 64.0f);
            else if (i == j)  v = degs[i] + pr::EPSV;
            else              v = -Cs[i][j];
            Sys[i][j] = v;
        }
        __syncthreads();

        // Gauss-Jordan (no pivoting; system is strictly diagonally dominant)
        for (int k = 0; k < pr::NN; k++) {
            const int i = rslot + (rslot >= k ? 1 : 0);
            const float f = Sys[i][k] / Sys[k][k];
            for (int j = k + 1 + jlane; j <= 65; j += 8)
                Sys[i][j] -= f * Sys[k][j];
            __syncthreads();
        }
        if (tid < pr::NN) pvec[tid] = Sys[tid][65] / Sys[tid][tid];
        __syncthreads();

        // flow + update (bitwise-symmetric -> explicit symmetrization is identity)
        for (int idx = tid; idx < pr::NN * pr::NN; idx += 512) {
            const int i = idx / pr::NN, j = idx % pr::NN;
            const float c  = Cs[i][j];
            const float fl = c * (pvec[i] - pvec[j]);
            qh[(size_t)t * pr::NN * pr::NN + idx] = fl;
            const float af = fabsf(fl);
            const float r  = af / (1.0f + af);
            float cn = c + pr::DTV * (r - pr::GAMMAV * c);
            cn = (i == j) ? 0.0f : fmaxf(cn, pr::FLOORV);
            Cs[i][j] = cn;
            dh[(size_t)(t + 1) * pr::NN * pr::NN + idx] = cn;
            stable_acc += fabsf(cn - c);
        }
        __syncthreads();
    }

    // group_flow from last flow (q_hist[:, -1, 1:, :] abs row sums)
    if (tid >= 1 && tid < pr::NN) {
        const float* qrow = qh + (size_t)7 * pr::NN * pr::NN + tid * pr::NN;
        float s = 0.0f;
        for (int j = 0; j < pr::NN; j++) s += fabsf(qrow[j]);
        g_gf[b * pr::NG + (tid - 1)] = s;
    }

    // aux_sparse partial: sum C_final[1:,1:]
    float sp = 0.0f;
    for (int idx = tid; idx < pr::NG * pr::NG; idx += 512)
        sp += Cs[idx / pr::NG + 1][idx % pr::NG + 1];
    red[tid] = sp;
    __syncthreads();
    for (int o = 256; o > 0; o >>= 1) {
        if (tid < o) red[tid] += red[tid + o];
        __syncthreads();
    }
    if (tid == 0) g_aux_sp[b] = red[0];
    __syncthreads();
    red[tid] = stable_acc;
    __syncthreads();
    for (int o = 256; o > 0; o >>= 1) {
        if (tid < o) red[tid] += red[tid + o];
        __syncthreads();
    }
    if (tid == 0) g_aux_st[b] = red[0];
    __syncthreads();

    // routing: C_final[1:,1:] normalized by row sums (clip 1e-6)
    if (tid >= 1 && tid < pr::NN) {
        float rs = 0.0f;
        for (int j = 1; j < pr::NN; j++) rs += Cs[tid][j];
        degs[tid] = fmaxf(rs, 1e-6f);
    }
    __syncthreads();
    float* rout = out + pr::OFF_ROUT + (size_t)b * pr::NG * pr::NG;
    for (int idx = tid; idx < pr::NG * pr::NG; idx += 512) {
        const int i = idx / pr::NG + 1, j = idx % pr::NG + 1;
        rout[idx] = Cs[i][j] / degs[i];
    }
}

// ======================================================================
// K5: scores, exact top-k (O(P^2) rank with jax tie-break), masks, gid.
// One block per batch, 576 threads.
// ======================================================================
__global__ void __launch_bounds__(576) k_scores(const float* __restrict__ ls,
                                                const int* gh_p, const int* gw_p,
                                                float* __restrict__ out) {
    __shared__ float ts[pr::P];
    __shared__ float normg[pr::NG];
    __shared__ float sred[20];
    __shared__ float stats[4];   // gmean, gstd, lmean, lstd

    const int b = blockIdx.x;
    const int tid = threadIdx.x;

    // group score stats (64 values, serial on thread 0 — trivial, deterministic)
    if (tid == 0) {
        float m = 0.0f;
        for (int g = 0; g < pr::NG; g++) m += g_gf[b * pr::NG + g];
        m /= (float)pr::NG;
        float v = 0.0f;
        for (int g = 0; g < pr::NG; g++) {
            const float d = g_gf[b * pr::NG + g] - m;
            v += d * d;
        }
        stats[0] = m;
        stats[1] = fmaxf(sqrtf(v / (float)(pr::NG - 1)), 1e-6f);
    }

    // local score stats over P=576 (ddof=1)
    const float x = ls[(size_t)b * pr::P + tid];
    float s = x;
#pragma unroll
    for (int o = 16; o > 0; o >>= 1) s += __shfl_down_sync(0xffffffffu, s, o);
    if ((tid & 31) == 0) sred[tid >> 5] = s;
    __syncthreads();
    if (tid == 0) {
        float m = 0.0f;
        for (int w = 0; w < 18; w++) m += sred[w];
        stats[2] = m / (float)pr::P;
    }
    __syncthreads();
    const float dv = x - stats[2];
    float s2 = dv * dv;
#pragma unroll
    for (int o = 16; o > 0; o >>= 1) s2 += __shfl_down_sync(0xffffffffu, s2, o);
    if ((tid & 31) == 0) sred[tid >> 5] = s2;
    __syncthreads();
    if (tid == 0) {
        float v = 0.0f;
        for (int w = 0; w < 18; w++) v += sred[w];
        stats[3] = fmaxf(sqrtf(v / (float)(pr::P - 1)), 1e-6f);
    }
    if (tid < pr::NG)
        normg[tid] = (g_gf[b * pr::NG + tid] - stats[0]) / stats[1];
    __syncthreads();

    const int GH = gh_p ? *gh_p : 24;
    const int GW = gw_p ? *gw_p : 24;
    const int gh = (GH + 7) / 8, gw = (GW + 7) / 8;
    const int r = tid / GW, c = tid % GW;
    const int gidp = min(r / gh, 7) * 8 + min(c / gw, 7);

    const float gs = normg[gidp];
    const float myscore = gs + 0.5f * (x - stats[2]) / stats[3];
    ts[tid] = myscore;
    out[pr::OFF_GSC + b * pr::P + tid] = gs;
    out[pr::OFF_GID + b * pr::P + tid] = (float)gidp;
    __syncthreads();

    // exact rank: count of strictly-better (score, -index) keys
    int cnt = 0;
    for (int q = 0; q < pr::P; q++) {
        const float tq = ts[q];
        cnt += (tq > myscore) || (tq == myscore && q < tid);
    }
    const float keep = (cnt < pr::KEEPC) ? 1.0f : 0.0f;
    out[pr::OFF_PATCH + b * pr::P + tid] = keep;
    out[pr::OFF_KEEP + b * (pr::P + 1) + 1 + tid] = keep;
    if (tid == 0) out[pr::OFF_KEEP + b * (pr::P + 1)] = 1.0f;
}

// ======================================================================
// K6: aux scalar finalization (fixed summation order, deterministic)
// ======================================================================
__global__ void k_aux(float* __restrict__ out) {
    if (threadIdx.x == 0) {
        float s1 = 0.0f, s2 = 0.0f;
        for (int b = 0; b < pr::B; b++) {
            s1 += g_aux_sp[b];
            s2 += g_aux_st[b];
        }
        out[pr::OFF_SPARSE] = s1 / (float)pr::B;
        out[pr::OFF_STABLE] = s2 / (float)pr::B;
    }
}

// ======================================================================
extern "C" void kernel_launch(void* const* d_in, const int* in_sizes, int n_in,
                              void* d_out, int out_size) {
    const float* tokens = (const float*)d_in[0];
    const float* cls    = (const float*)d_in[1];
    const float* W      = (const float*)d_in[2];
    const float* ls     = (const float*)d_in[3];
    const int* ghp = (n_in > 4) ? (const int*)d_in[4] : nullptr;
    const int* gwp = (n_in > 5) ? (const int*)d_in[5] : nullptr;
    float* out = (float*)d_out;

    k_groups<<<pr::B * pr::NN, 256>>>(tokens, cls, ghp, gwp);

    dim3 gg(pr::D / 64, (pr::B * pr::NN + 127) / 128);   // 12 x 33
    k_gemm<<<gg, 256>>>(W);

    k_rownorm<<<pr::B * pr::NN, 256>>>();
    k_gram<<<pr::B, 256>>>(out);
    k_dyn<<<pr::B, 512>>>(out);
    k_scores<<<pr::B, pr::P>>>(ls, ghp, gwp, out);
    k_aux<<<1, 32>>>(out);
}

// round 15
// speedup vs baseline: 1.1589x; 1.1589x over previous
#include <cuda_runtime.h>
#include <math.h>

// ---------------- problem constants (fixed by setup_inputs) ----------------
namespace pr {
constexpr int B  = 64;
constexpr int P  = 576;
constexpr int D  = 768;
constexpr int NG = 64;
constexpr int NN = 65;      // GROUPS + 1
constexpr int STEPS = 8;
constexpr float FLOORV = 1e-4f;
constexpr float EPSV   = 1e-4f;
constexpr float DTV    = 0.1f;
constexpr float GAMMAV = 0.1f;
constexpr int   KEEPC  = 288;   // round(576 * 0.5)
constexpr int   KCH    = 6;     // gram K-chunks (768/128)

// output tuple layout (flattened, float32):
// keep_mask(B,577), patch_keep_mask(B,576), gid(B,576), group_scores(B,576),
// d_hist(B,9,65,65), q_hist(B,8,65,65), routing(B,64,64), aux_sparse, aux_stable
constexpr int OFF_KEEP   = 0;
constexpr int OFF_PATCH  = OFF_KEEP  + B * (P + 1);
constexpr int OFF_GID    = OFF_PATCH + B * P;
constexpr int OFF_GSC    = OFF_GID   + B * P;
constexpr int OFF_DH     = OFF_GSC   + B * P;
constexpr int OFF_QH     = OFF_DH    + B * 9 * NN * NN;
constexpr int OFF_ROUT   = OFF_QH    + B * 8 * NN * NN;
constexpr int OFF_SPARSE = OFF_ROUT  + B * NG * NG;
constexpr int OFF_STABLE = OFF_SPARSE + 1;
}

// ---------------- scratch (__device__ globals; no allocation) ----------------
__device__ float g_nodes[pr::B * pr::NN * pr::D];   // (B,65,768)
__device__ float g_proj [pr::B * pr::NN * pr::D];   // (B,65,768) RAW (unnormalized)
__device__ float g_gpart[pr::B * pr::KCH * pr::NN * pr::NN]; // gram partials
__device__ float g_gf   [pr::B * pr::NG];           // group_flow
__device__ float g_aux_sp[pr::B];
__device__ float g_aux_st[pr::B];

// ======================================================================
// K1: group means + nodes assembly.  grid = B*65 blocks, 256 threads.
// ======================================================================
__global__ void k_groups(const float* __restrict__ tokens,
                         const float* __restrict__ cls,
                         const int* gh_p, const int* gw_p) {
    const int b = blockIdx.x / pr::NN;
    const int n = blockIdx.x % pr::NN;
    float* dst = g_nodes + ((size_t)b * pr::NN + n) * pr::D;

    if (n == 0) {
        for (int d = threadIdx.x; d < pr::D; d += blockDim.x)
            dst[d] = cls[(size_t)b * pr::D + d];
        return;
    }
    const int GH = gh_p ? *gh_p : 24;
    const int GW = gw_p ? *gw_p : 24;
    const int g  = n - 1;
    const int gh = (GH + 7) / 8;
    const int gw = (GW + 7) / 8;
    const int gr = g / 8, gc = g % 8;
    int r0 = gr * gh;  int r1 = (gr == 7) ? GH : min((gr + 1) * gh, GH);
    int c0 = gc * gw;  int c1 = (gc == 7) ? GW : min((gc + 1) * gw, GW);
    if (r0 > GH) r0 = GH;
    if (c0 > GW) c0 = GW;
    const int cnt = (r1 > r0 && c1 > c0) ? (r1 - r0) * (c1 - c0) : 0;
    const float inv = 1.0f / (float)max(cnt, 1);

    for (int d = threadIdx.x; d < pr::D; d += blockDim.x) {
        float acc = 0.0f;
        for (int r = r0; r < r1; r++)
            for (int c = c0; c < c1; c++)
                acc += tokens[((size_t)b * pr::P + r * GW + c) * pr::D + d];
        dst[d] = acc * inv;
    }
}

// ======================================================================
// K2: proj = nodes @ W^T   (M=4160, N=768, K=768, fp32, NT layout)
// 128x64 block tile, 16 K-slice, 256 threads, 8x4 micro tile.
// Writes RAW proj (normalization is folded into the Gram stage).
// ======================================================================
__global__ void __launch_bounds__(256) k_gemm(const float* __restrict__ W) {
    __shared__ float As[16][128 + 4];
    __shared__ float Bs[16][64 + 4];
    const int M = pr::B * pr::NN;                 // 4160
    const int m0 = blockIdx.y * 128;
    const int n0 = blockIdx.x * 64;
    const int tid = threadIdx.x;
    const int tx = tid & 15, ty = tid >> 4;       // 16 x 16 thread grid
    const int lr = tid >> 2, lc = tid & 3;        // loader layout

    float acc[8][4];
#pragma unroll
    for (int i = 0; i < 8; i++)
#pragma unroll
        for (int j = 0; j < 4; j++) acc[i][j] = 0.0f;

    const float* A = g_nodes;
    for (int k0 = 0; k0 < pr::D; k0 += 16) {
#pragma unroll
        for (int h = 0; h < 2; h++) {
            const int m = m0 + lr + h * 64;
            float4 v = make_float4(0.f, 0.f, 0.f, 0.f);
            if (m < M) v = *(const float4*)(A + (size_t)m * pr::D + k0 + lc * 4);
            As[lc * 4 + 0][lr + h * 64] = v.x;
            As[lc * 4 + 1][lr + h * 64] = v.y;
            As[lc * 4 + 2][lr + h * 64] = v.z;
            As[lc * 4 + 3][lr + h * 64] = v.w;
        }
        {
            const float4 v = *(const float4*)(W + (size_t)(n0 + lr) * pr::D + k0 + lc * 4);
            Bs[lc * 4 + 0][lr] = v.x;
            Bs[lc * 4 + 1][lr] = v.y;
            Bs[lc * 4 + 2][lr] = v.z;
            Bs[lc * 4 + 3][lr] = v.w;
        }
        __syncthreads();
#pragma unroll
        for (int kk = 0; kk < 16; kk++) {
            float a[8], bv[4];
#pragma unroll
            for (int i = 0; i < 8; i++) a[i] = As[kk][ty * 8 + i];
#pragma unroll
            for (int j = 0; j < 4; j++) bv[j] = Bs[kk][tx * 4 + j];
#pragma unroll
            for (int i = 0; i < 8; i++)
#pragma unroll
                for (int j = 0; j < 4; j++) acc[i][j] += a[i] * bv[j];
        }
        __syncthreads();
    }
#pragma unroll
    for (int i = 0; i < 8; i++) {
        const int m = m0 + ty * 8 + i;
        if (m < M) {
            float4 v = make_float4(acc[i][0], acc[i][1], acc[i][2], acc[i][3]);
            *(float4*)(g_proj + (size_t)m * pr::D + n0 + tx * 4) = v;
        }
    }
}

// ======================================================================
// K3a: Gram partials. grid = (B, KCH) = (64, 6) blocks, 256 threads.
// Each block: stage 65x128 K-chunk in smem, 16x16 threads x 5x5 micro
// tiles over an 80x80 padded output -> partial G into g_gpart.
// ======================================================================
__global__ void __launch_bounds__(256) k_gram_part() {
    __shared__ float Ps[128][67];    // [k][n], stride 67 (coprime 32) -> conflict-free
    const int b  = blockIdx.x;
    const int kc = blockIdx.y;
    const int k0 = kc * 128;
    const float* __restrict__ Pb = g_proj + (size_t)b * pr::NN * pr::D;
    const int tid = threadIdx.x;

    for (int idx = tid; idx < pr::NN * 128; idx += 256) {
        const int n = idx >> 7, k = idx & 127;
        Ps[k][n] = Pb[(size_t)n * pr::D + k0 + k];
    }
    __syncthreads();

    const int tx = tid & 15, ty = tid >> 4;
    int ii[5], jj[5];
#pragma unroll
    for (int u = 0; u < 5; u++) {
        ii[u] = min(ty * 5 + u, pr::NN - 1);
        jj[u] = min(tx * 5 + u, pr::NN - 1);
    }
    float acc[5][5];
#pragma unroll
    for (int u = 0; u < 5; u++)
#pragma unroll
        for (int v = 0; v < 5; v++) acc[u][v] = 0.0f;

#pragma unroll 4
    for (int k = 0; k < 128; k++) {
        float a[5], bv[5];
#pragma unroll
        for (int u = 0; u < 5; u++) a[u]  = Ps[k][ii[u]];
#pragma unroll
        for (int v = 0; v < 5; v++) bv[v] = Ps[k][jj[v]];
#pragma unroll
        for (int u = 0; u < 5; u++)
#pragma unroll
            for (int v = 0; v < 5; v++) acc[u][v] += a[u] * bv[v];
    }

    float* dst = g_gpart + ((size_t)b * pr::KCH + kc) * pr::NN * pr::NN;
#pragma unroll
    for (int u = 0; u < 5; u++) {
        const int i = ty * 5 + u;
        if (i >= pr::NN) break;
#pragma unroll
        for (int v = 0; v < 5; v++) {
            const int j = tx * 5 + v;
            if (j < pr::NN) dst[i * pr::NN + j] = acc[u][v];
        }
    }
}

// ======================================================================
// K3b: reduce partials, fold in row normalization, emit C0 -> d_hist[b,0].
// grid = B blocks, 256 threads.
//   n_i = max(sqrt(G_ii), 1e-12);  dot' = G_ij/(n_i n_j);  sq_i = G_ii/n_i^2
//   d2 = max(sq_i + sq_j - 2 dot', 0);  C = (i==j)?0:max(exp(-d2), FLOOR)
// ======================================================================
__global__ void __launch_bounds__(256) k_c0(float* __restrict__ out) {
    __shared__ float G[pr::NN * pr::NN];
    __shared__ float invn[pr::NN];
    __shared__ float sq[pr::NN];
    const int b = blockIdx.x;
    const int tid = threadIdx.x;
    const float* src = g_gpart + (size_t)b * pr::KCH * pr::NN * pr::NN;

    for (int idx = tid; idx < pr::NN * pr::NN; idx += 256) {
        float s = 0.0f;
#pragma unroll
        for (int c = 0; c < pr::KCH; c++)
            s += src[(size_t)c * pr::NN * pr::NN + idx];
        G[idx] = s;
    }
    __syncthreads();
    if (tid < pr::NN) {
        const float gii = G[tid * pr::NN + tid];
        const float n = fmaxf(sqrtf(gii), 1e-12f);
        invn[tid] = 1.0f / n;
        sq[tid] = gii / (n * n);
    }
    __syncthreads();

    float* dh0 = out + pr::OFF_DH + (size_t)b * 9 * pr::NN * pr::NN;
    for (int idx = tid; idx < pr::NN * pr::NN; idx += 256) {
        const int i = idx / pr::NN, j = idx % pr::NN;
        const float dot = G[idx] * invn[i] * invn[j];
        const float d2 = fmaxf(sq[i] + sq[j] - 2.0f * dot, 0.0f);
        dh0[idx] = (i == j) ? 0.0f : fmaxf(expf(-d2), pr::FLOORV);
    }
}

// ======================================================================
// K4: Physarum dynamics. One block per batch, 512 threads.
// 8 steps of: degree, diagonally-dominant 65x65 Gauss-Jordan solve, flow,
// conductance update. Writes d_hist/q_hist/routing directly to d_out.
// ======================================================================
__global__ void __launch_bounds__(512) k_dyn(float* __restrict__ out) {
    __shared__ float Cs[pr::NN][66];
    __shared__ float Sys[pr::NN][72];      // 66 used
    __shared__ float pvec[pr::NN];
    __shared__ float degs[pr::NN];
    __shared__ float red[512];

    const int b = blockIdx.x;
    const int tid = threadIdx.x;
    float* dh = out + pr::OFF_DH + (size_t)b * 9 * pr::NN * pr::NN;
    float* qh = out + pr::OFF_QH + (size_t)b * 8 * pr::NN * pr::NN;

    for (int idx = tid; idx < pr::NN * pr::NN; idx += 512)
        Cs[idx / pr::NN][idx % pr::NN] = dh[idx];
    __syncthreads();

    float stable_acc = 0.0f;
    const int rslot = tid >> 3;     // 0..63
    const int jlane = tid & 7;

    for (int t = 0; t < pr::STEPS; t++) {
        if (tid < pr::NN) {
            float s = 0.0f;
            for (int j = 0; j < pr::NN; j++) s += Cs[tid][j];
            degs[tid] = s;
        }
        __syncthreads();
        for (int idx = tid; idx < pr::NN * 66; idx += 512) {
            const int i = idx / 66, j = idx % 66;
            float v;
            if (j == 65)      v = (i == 0) ? 1.0f : (-1.0f / 64.0f);
            else if (i == j)  v = degs[i] + pr::EPSV;
            else              v = -Cs[i][j];
            Sys[i][j] = v;
        }
        __syncthreads();

        // Gauss-Jordan (no pivoting; strictly diagonally dominant)
        for (int k = 0; k < pr::NN; k++) {
            const int i = rslot + (rslot >= k ? 1 : 0);
            const float f = Sys[i][k] / Sys[k][k];
            for (int j = k + 1 + jlane; j <= 65; j += 8)
                Sys[i][j] -= f * Sys[k][j];
            __syncthreads();
        }
        if (tid < pr::NN) pvec[tid] = Sys[tid][65] / Sys[tid][tid];
        __syncthreads();

        // flow + update (bitwise-symmetric)
        for (int idx = tid; idx < pr::NN * pr::NN; idx += 512) {
            const int i = idx / pr::NN, j = idx % pr::NN;
            const float c  = Cs[i][j];
            const float fl = c * (pvec[i] - pvec[j]);
            qh[(size_t)t * pr::NN * pr::NN + idx] = fl;
            const float af = fabsf(fl);
            const float r  = af / (1.0f + af);
            float cn = c + pr::DTV * (r - pr::GAMMAV * c);
            cn = (i == j) ? 0.0f : fmaxf(cn, pr::FLOORV);
            Cs[i][j] = cn;
            dh[(size_t)(t + 1) * pr::NN * pr::NN + idx] = cn;
            stable_acc += fabsf(cn - c);
        }
        __syncthreads();
    }

    // group_flow from last flow
    if (tid >= 1 && tid < pr::NN) {
        const float* qrow = qh + (size_t)7 * pr::NN * pr::NN + tid * pr::NN;
        float s = 0.0f;
        for (int j = 0; j < pr::NN; j++) s += fabsf(qrow[j]);
        g_gf[b * pr::NG + (tid - 1)] = s;
    }

    // aux_sparse partial: sum C_final[1:,1:]
    float sp = 0.0f;
    for (int idx = tid; idx < pr::NG * pr::NG; idx += 512)
        sp += Cs[idx / pr::NG + 1][idx % pr::NG + 1];
    red[tid] = sp;
    __syncthreads();
    for (int o = 256; o > 0; o >>= 1) {
        if (tid < o) red[tid] += red[tid + o];
        __syncthreads();
    }
    if (tid == 0) g_aux_sp[b] = red[0];
    __syncthreads();
    red[tid] = stable_acc;
    __syncthreads();
    for (int o = 256; o > 0; o >>= 1) {
        if (tid < o) red[tid] += red[tid + o];
        __syncthreads();
    }
    if (tid == 0) g_aux_st[b] = red[0];
    __syncthreads();

    // routing: C_final[1:,1:] normalized by row sums (clip 1e-6)
    if (tid >= 1 && tid < pr::NN) {
        float rs = 0.0f;
        for (int j = 1; j < pr::NN; j++) rs += Cs[tid][j];
        degs[tid] = fmaxf(rs, 1e-6f);
    }
    __syncthreads();
    float* rout = out + pr::OFF_ROUT + (size_t)b * pr::NG * pr::NG;
    for (int idx = tid; idx < pr::NG * pr::NG; idx += 512) {
        const int i = idx / pr::NG + 1, j = idx % pr::NG + 1;
        rout[idx] = Cs[i][j] / degs[i];
    }
}

// ======================================================================
// K5: scores, exact top-k (O(P^2) rank with jax tie-break), masks, gid.
// ======================================================================
__global__ void __launch_bounds__(576) k_scores(const float* __restrict__ ls,
                                                const int* gh_p, const int* gw_p,
                                                float* __restrict__ out) {
    __shared__ float ts[pr::P];
    __shared__ float normg[pr::NG];
    __shared__ float sred[20];
    __shared__ float stats[4];

    const int b = blockIdx.x;
    const int tid = threadIdx.x;

    if (tid == 0) {
        float m = 0.0f;
        for (int g = 0; g < pr::NG; g++) m += g_gf[b * pr::NG + g];
        m /= (float)pr::NG;
        float v = 0.0f;
        for (int g = 0; g < pr::NG; g++) {
            const float d = g_gf[b * pr::NG + g] - m;
            v += d * d;
        }
        stats[0] = m;
        stats[1] = fmaxf(sqrtf(v / (float)(pr::NG - 1)), 1e-6f);
    }

    const float x = ls[(size_t)b * pr::P + tid];
    float s = x;
#pragma unroll
    for (int o = 16; o > 0; o >>= 1) s += __shfl_down_sync(0xffffffffu, s, o);
    if ((tid & 31) == 0) sred[tid >> 5] = s;
    __syncthreads();
    if (tid == 0) {
        float m = 0.0f;
        for (int w = 0; w < 18; w++) m += sred[w];
        stats[2] = m / (float)pr::P;
    }
    __syncthreads();
    const float dv = x - stats[2];
    float s2 = dv * dv;
#pragma unroll
    for (int o = 16; o > 0; o >>= 1) s2 += __shfl_down_sync(0xffffffffu, s2, o);
    if ((tid & 31) == 0) sred[tid >> 5] = s2;
    __syncthreads();
    if (tid == 0) {
        float v = 0.0f;
        for (int w = 0; w < 18; w++) v += sred[w];
        stats[3] = fmaxf(sqrtf(v / (float)(pr::P - 1)), 1e-6f);
    }
    if (tid < pr::NG)
        normg[tid] = (g_gf[b * pr::NG + tid] - stats[0]) / stats[1];
    __syncthreads();

    const int GH = gh_p ? *gh_p : 24;
    const int GW = gw_p ? *gw_p : 24;
    const int gh = (GH + 7) / 8, gw = (GW + 7) / 8;
    const int r = tid / GW, c = tid % GW;
    const int gidp = min(r / gh, 7) * 8 + min(c / gw, 7);

    const float gs = normg[gidp];
    const float myscore = gs + 0.5f * (x - stats[2]) / stats[3];
    ts[tid] = myscore;
    out[pr::OFF_GSC + b * pr::P + tid] = gs;
    out[pr::OFF_GID + b * pr::P + tid] = (float)gidp;
    __syncthreads();

    int cnt = 0;
    for (int q = 0; q < pr::P; q++) {
        const float tq = ts[q];
        cnt += (tq > myscore) || (tq == myscore && q < tid);
    }
    const float keep = (cnt < pr::KEEPC) ? 1.0f : 0.0f;
    out[pr::OFF_PATCH + b * pr::P + tid] = keep;
    out[pr::OFF_KEEP + b * (pr::P + 1) + 1 + tid] = keep;
    if (tid == 0) out[pr::OFF_KEEP + b * (pr::P + 1)] = 1.0f;
}

// ======================================================================
// K6: aux scalar finalization (fixed order, deterministic)
// ======================================================================
__global__ void k_aux(float* __restrict__ out) {
    if (threadIdx.x == 0) {
        float s1 = 0.0f, s2 = 0.0f;
        for (int b = 0; b < pr::B; b++) {
            s1 += g_aux_sp[b];
            s2 += g_aux_st[b];
        }
        out[pr::OFF_SPARSE] = s1 / (float)pr::B;
        out[pr::OFF_STABLE] = s2 / (float)pr::B;
    }
}

// ======================================================================
extern "C" void kernel_launch(void* const* d_in, const int* in_sizes, int n_in,
                              void* d_out, int out_size) {
    const float* tokens = (const float*)d_in[0];
    const float* cls    = (const float*)d_in[1];
    const float* W      = (const float*)d_in[2];
    const float* ls     = (const float*)d_in[3];
    const int* ghp = (n_in > 4) ? (const int*)d_in[4] : nullptr;
    const int* gwp = (n_in > 5) ? (const int*)d_in[5] : nullptr;
    float* out = (float*)d_out;

    k_groups<<<pr::B * pr::NN, 256>>>(tokens, cls, ghp, gwp);

    dim3 gg(pr::D / 64, (pr::B * pr::NN + 127) / 128);   // 12 x 33
    k_gemm<<<gg, 256>>>(W);

    k_gram_part<<<dim3(pr::B, pr::KCH), 256>>>();
    k_c0<<<pr::B, 256>>>(out);
    k_dyn<<<pr::B, 512>>>(out);
    k_scores<<<pr::B, pr::P>>>(ls, ghp, gwp, out);
    k_aux<<<1, 32>>>(out);
}

// round 16
// speedup vs baseline: 1.2113x; 1.0452x over previous
#include <cuda_runtime.h>
#include <math.h>
#include <stdint.h>

// ---------------- problem constants (fixed by setup_inputs) ----------------
namespace pr {
constexpr int B  = 64;
constexpr int P  = 576;
constexpr int D  = 768;
constexpr int NG = 64;
constexpr int NN = 65;      // GROUPS + 1
constexpr int STEPS = 8;
constexpr float FLOORV = 1e-4f;
constexpr float EPSV   = 1e-4f;
constexpr float DTV    = 0.1f;
constexpr float GAMMAV = 0.1f;
constexpr int   KEEPC  = 288;   // round(576 * 0.5)
constexpr int   KCH    = 6;     // gram K-chunks (768/128)

constexpr int OFF_KEEP   = 0;
constexpr int OFF_PATCH  = OFF_KEEP  + B * (P + 1);
constexpr int OFF_GID    = OFF_PATCH + B * P;
constexpr int OFF_GSC    = OFF_GID   + B * P;
constexpr int OFF_DH     = OFF_GSC   + B * P;
constexpr int OFF_QH     = OFF_DH    + B * 9 * NN * NN;
constexpr int OFF_ROUT   = OFF_QH    + B * 8 * NN * NN;
constexpr int OFF_SPARSE = OFF_ROUT  + B * NG * NG;
constexpr int OFF_STABLE = OFF_SPARSE + 1;
}

// ---------------- scratch (__device__ globals; no allocation) ----------------
__device__ float g_nodes[pr::B * pr::NN * pr::D];   // (B,65,768)
__device__ float g_proj [pr::B * pr::NN * pr::D];   // (B,65,768) RAW (unnormalized)
__device__ float g_gpart[pr::B * pr::KCH * pr::NN * pr::NN];
__device__ float g_gf   [pr::B * pr::NG];
__device__ float g_aux_sp[pr::B];
__device__ float g_aux_st[pr::B];

// ======================================================================
// K1: group means + nodes assembly.  grid = B*65 blocks, 256 threads.
// ======================================================================
__global__ void k_groups(const float* __restrict__ tokens,
                         const float* __restrict__ cls,
                         const int* gh_p, const int* gw_p) {
    const int b = blockIdx.x / pr::NN;
    const int n = blockIdx.x % pr::NN;
    float* dst = g_nodes + ((size_t)b * pr::NN + n) * pr::D;

    if (n == 0) {
        for (int d = threadIdx.x; d < pr::D; d += blockDim.x)
            dst[d] = cls[(size_t)b * pr::D + d];
        return;
    }
    const int GH = gh_p ? *gh_p : 24;
    const int GW = gw_p ? *gw_p : 24;
    const int g  = n - 1;
    const int gh = (GH + 7) / 8;
    const int gw = (GW + 7) / 8;
    const int gr = g / 8, gc = g % 8;
    int r0 = gr * gh;  int r1 = (gr == 7) ? GH : min((gr + 1) * gh, GH);
    int c0 = gc * gw;  int c1 = (gc == 7) ? GW : min((gc + 1) * gw, GW);
    if (r0 > GH) r0 = GH;
    if (c0 > GW) c0 = GW;
    const int cnt = (r1 > r0 && c1 > c0) ? (r1 - r0) * (c1 - c0) : 0;
    const float inv = 1.0f / (float)max(cnt, 1);

    for (int d = threadIdx.x; d < pr::D; d += blockDim.x) {
        float acc = 0.0f;
        for (int r = r0; r < r1; r++)
            for (int c = c0; c < c1; c++)
                acc += tokens[((size_t)b * pr::P + r * GW + c) * pr::D + d];
        dst[d] = acc * inv;
    }
}

// ======================================================================
// K2: tensor-core GEMM, 3xTF32 split. proj = nodes @ W^T
// M=4160, N=768, K=768. Block 128x64, 8 warps (64x16 each), k-tile 32.
// ======================================================================
__device__ __forceinline__ void split_tf32(float v, uint32_t& hi, uint32_t& lo) {
    uint32_t h;
    asm("cvt.rna.tf32.f32 %0, %1;" : "=r"(h) : "f"(v));
    hi = h;
    lo = __float_as_uint(v - __uint_as_float(h));
}

#define MMA_TF32(d0,d1,d2,d3,a0,a1,a2,a3,b0,b1)                                 \
    asm volatile("mma.sync.aligned.m16n8k8.row.col.f32.tf32.tf32.f32 "          \
                 "{%0,%1,%2,%3},{%4,%5,%6,%7},{%8,%9},{%0,%1,%2,%3};"           \
                 : "+f"(d0), "+f"(d1), "+f"(d2), "+f"(d3)                       \
                 : "r"(a0), "r"(a1), "r"(a2), "r"(a3), "r"(b0), "r"(b1))

__global__ void __launch_bounds__(256) k_gemm_tc(const float* __restrict__ W) {
    __shared__ float As[32][133];   // [k][m], pad 5 -> conflict-free transposed store
    __shared__ float Bs[32][69];    // [k][n], pad 5
    const int M  = pr::B * pr::NN;  // 4160
    const int m0 = blockIdx.y * 128;
    const int n0 = blockIdx.x * 64;
    const int tid  = threadIdx.x;
    const int wid  = tid >> 5;
    const int lane = tid & 31;
    const int wm = (wid & 1) * 64;      // warp m-offset within block
    const int wn = (wid >> 1) * 16;     // warp n-offset within block
    const int g = lane >> 2, c = lane & 3;

    float acc[4][2][4];
#pragma unroll
    for (int mt = 0; mt < 4; mt++)
#pragma unroll
        for (int nt = 0; nt < 2; nt++)
#pragma unroll
            for (int r = 0; r < 4; r++) acc[mt][nt][r] = 0.0f;

    const int am = tid >> 1;                 // 0..127 (A loader row)
    const int akb = (tid & 1) * 16;          // A loader k base
    const int bn = tid >> 2;                 // 0..63 (B loader row)
    const int bkb = (tid & 3) * 8;           // B loader k base

    for (int k0 = 0; k0 < pr::D; k0 += 32) {
        // ---- stage A (transpose to [k][m]) ----
        {
            const int m = m0 + am;
            const float* src = g_nodes + (size_t)m * pr::D + k0 + akb;
#pragma unroll
            for (int f = 0; f < 4; f++) {
                float4 v = make_float4(0.f, 0.f, 0.f, 0.f);
                if (m < M) v = *(const float4*)(src + f * 4);
                As[akb + f * 4 + 0][am] = v.x;
                As[akb + f * 4 + 1][am] = v.y;
                As[akb + f * 4 + 2][am] = v.z;
                As[akb + f * 4 + 3][am] = v.w;
            }
        }
        // ---- stage B (transpose to [k][n]) ----
        {
            const float* src = W + (size_t)(n0 + bn) * pr::D + k0 + bkb;
#pragma unroll
            for (int f = 0; f < 2; f++) {
                const float4 v = *(const float4*)(src + f * 4);
                Bs[bkb + f * 4 + 0][bn] = v.x;
                Bs[bkb + f * 4 + 1][bn] = v.y;
                Bs[bkb + f * 4 + 2][bn] = v.z;
                Bs[bkb + f * 4 + 3][bn] = v.w;
            }
        }
        __syncthreads();

#pragma unroll
        for (int ks = 0; ks < 4; ks++) {
            const int kk = ks * 8;
            uint32_t ah[4][4], al[4][4], bh[2][2], bl[2][2];
#pragma unroll
            for (int mt = 0; mt < 4; mt++) {
                const int mr = wm + mt * 16 + g;
                split_tf32(As[kk + c    ][mr    ], ah[mt][0], al[mt][0]);
                split_tf32(As[kk + c    ][mr + 8], ah[mt][1], al[mt][1]);
                split_tf32(As[kk + c + 4][mr    ], ah[mt][2], al[mt][2]);
                split_tf32(As[kk + c + 4][mr + 8], ah[mt][3], al[mt][3]);
            }
#pragma unroll
            for (int nt = 0; nt < 2; nt++) {
                const int nc = wn + nt * 8 + g;
                split_tf32(Bs[kk + c    ][nc], bh[nt][0], bl[nt][0]);
                split_tf32(Bs[kk + c + 4][nc], bh[nt][1], bl[nt][1]);
            }
#pragma unroll
            for (int mt = 0; mt < 4; mt++)
#pragma unroll
                for (int nt = 0; nt < 2; nt++) {
                    float* d = acc[mt][nt];
                    MMA_TF32(d[0], d[1], d[2], d[3],
                             ah[mt][0], ah[mt][1], ah[mt][2], ah[mt][3],
                             bh[nt][0], bh[nt][1]);
                    MMA_TF32(d[0], d[1], d[2], d[3],
                             ah[mt][0], ah[mt][1], ah[mt][2], ah[mt][3],
                             bl[nt][0], bl[nt][1]);
                    MMA_TF32(d[0], d[1], d[2], d[3],
                             al[mt][0], al[mt][1], al[mt][2], al[mt][3],
                             bh[nt][0], bh[nt][1]);
                }
        }
        __syncthreads();
    }

    // ---- epilogue: D fragment -> g_proj[m][768] ----
#pragma unroll
    for (int mt = 0; mt < 4; mt++) {
        const int r0 = m0 + wm + mt * 16 + g;
        const int r1 = r0 + 8;
#pragma unroll
        for (int nt = 0; nt < 2; nt++) {
            const int col = n0 + wn + nt * 8 + 2 * c;
            if (r0 < M)
                *(float2*)(g_proj + (size_t)r0 * pr::D + col) =
                    make_float2(acc[mt][nt][0], acc[mt][nt][1]);
            if (r1 < M)
                *(float2*)(g_proj + (size_t)r1 * pr::D + col) =
                    make_float2(acc[mt][nt][2], acc[mt][nt][3]);
        }
    }
}

// ======================================================================
// K3a: Gram partials. grid = (B, KCH) = (64, 6), 256 threads.
// ======================================================================
__global__ void __launch_bounds__(256) k_gram_part() {
    __shared__ float Ps[128][67];
    const int b  = blockIdx.x;
    const int kc = blockIdx.y;
    const int k0 = kc * 128;
    const float* __restrict__ Pb = g_proj + (size_t)b * pr::NN * pr::D;
    const int tid = threadIdx.x;

    for (int idx = tid; idx < pr::NN * 128; idx += 256) {
        const int n = idx >> 7, k = idx & 127;
        Ps[k][n] = Pb[(size_t)n * pr::D + k0 + k];
    }
    __syncthreads();

    const int tx = tid & 15, ty = tid >> 4;
    int ii[5], jj[5];
#pragma unroll
    for (int u = 0; u < 5; u++) {
        ii[u] = min(ty * 5 + u, pr::NN - 1);
        jj[u] = min(tx * 5 + u, pr::NN - 1);
    }
    float acc[5][5];
#pragma unroll
    for (int u = 0; u < 5; u++)
#pragma unroll
        for (int v = 0; v < 5; v++) acc[u][v] = 0.0f;

#pragma unroll 4
    for (int k = 0; k < 128; k++) {
        float a[5], bv[5];
#pragma unroll
        for (int u = 0; u < 5; u++) a[u]  = Ps[k][ii[u]];
#pragma unroll
        for (int v = 0; v < 5; v++) bv[v] = Ps[k][jj[v]];
#pragma unroll
        for (int u = 0; u < 5; u++)
#pragma unroll
            for (int v = 0; v < 5; v++) acc[u][v] += a[u] * bv[v];
    }

    float* dst = g_gpart + ((size_t)b * pr::KCH + kc) * pr::NN * pr::NN;
#pragma unroll
    for (int u = 0; u < 5; u++) {
        const int i = ty * 5 + u;
        if (i >= pr::NN) break;
#pragma unroll
        for (int v = 0; v < 5; v++) {
            const int j = tx * 5 + v;
            if (j < pr::NN) dst[i * pr::NN + j] = acc[u][v];
        }
    }
}

// ======================================================================
// K3b: reduce partials + folded normalization -> C0 -> d_hist[b,0].
// ======================================================================
__global__ void __launch_bounds__(256) k_c0(float* __restrict__ out) {
    __shared__ float G[pr::NN * pr::NN];
    __shared__ float invn[pr::NN];
    __shared__ float sq[pr::NN];
    const int b = blockIdx.x;
    const int tid = threadIdx.x;
    const float* src = g_gpart + (size_t)b * pr::KCH * pr::NN * pr::NN;

    for (int idx = tid; idx < pr::NN * pr::NN; idx += 256) {
        float s = 0.0f;
#pragma unroll
        for (int c = 0; c < pr::KCH; c++)
            s += src[(size_t)c * pr::NN * pr::NN + idx];
        G[idx] = s;
    }
    __syncthreads();
    if (tid < pr::NN) {
        const float gii = G[tid * pr::NN + tid];
        const float n = fmaxf(sqrtf(gii), 1e-12f);
        invn[tid] = 1.0f / n;
        sq[tid] = gii / (n * n);
    }
    __syncthreads();

    float* dh0 = out + pr::OFF_DH + (size_t)b * 9 * pr::NN * pr::NN;
    for (int idx = tid; idx < pr::NN * pr::NN; idx += 256) {
        const int i = idx / pr::NN, j = idx % pr::NN;
        const float dot = G[idx] * invn[i] * invn[j];
        const float d2 = fmaxf(sq[i] + sq[j] - 2.0f * dot, 0.0f);
        dh0[idx] = (i == j) ? 0.0f : fmaxf(expf(-d2), pr::FLOORV);
    }
}

// ======================================================================
// K4: Physarum dynamics. One block per batch, 512 threads.
// ======================================================================
__global__ void __launch_bounds__(512) k_dyn(float* __restrict__ out) {
    __shared__ float Cs[pr::NN][66];
    __shared__ float Sys[pr::NN][72];
    __shared__ float pvec[pr::NN];
    __shared__ float degs[pr::NN];
    __shared__ float red[512];

    const int b = blockIdx.x;
    const int tid = threadIdx.x;
    float* dh = out + pr::OFF_DH + (size_t)b * 9 * pr::NN * pr::NN;
    float* qh = out + pr::OFF_QH + (size_t)b * 8 * pr::NN * pr::NN;

    for (int idx = tid; idx < pr::NN * pr::NN; idx += 512)
        Cs[idx / pr::NN][idx % pr::NN] = dh[idx];
    __syncthreads();

    float stable_acc = 0.0f;
    const int rslot = tid >> 3;
    const int jlane = tid & 7;

    for (int t = 0; t < pr::STEPS; t++) {
        if (tid < pr::NN) {
            float s = 0.0f;
            for (int j = 0; j < pr::NN; j++) s += Cs[tid][j];
            degs[tid] = s;
        }
        __syncthreads();
        for (int idx = tid; idx < pr::NN * 66; idx += 512) {
            const int i = idx / 66, j = idx % 66;
            float v;
            if (j == 65)      v = (i == 0) ? 1.0f : (-1.0f / 64.0f);
            else if (i == j)  v = degs[i] + pr::EPSV;
            else              v = -Cs[i][j];
            Sys[i][j] = v;
        }
        __syncthreads();

        for (int k = 0; k < pr::NN; k++) {
            const int i = rslot + (rslot >= k ? 1 : 0);
            const float f = Sys[i][k] / Sys[k][k];
            for (int j = k + 1 + jlane; j <= 65; j += 8)
                Sys[i][j] -= f * Sys[k][j];
            __syncthreads();
        }
        if (tid < pr::NN) pvec[tid] = Sys[tid][65] / Sys[tid][tid];
        __syncthreads();

        for (int idx = tid; idx < pr::NN * pr::NN; idx += 512) {
            const int i = idx / pr::NN, j = idx % pr::NN;
            const float c  = Cs[i][j];
            const float fl = c * (pvec[i] - pvec[j]);
            qh[(size_t)t * pr::NN * pr::NN + idx] = fl;
            const float af = fabsf(fl);
            const float r  = af / (1.0f + af);
            float cn = c + pr::DTV * (r - pr::GAMMAV * c);
            cn = (i == j) ? 0.0f : fmaxf(cn, pr::FLOORV);
            Cs[i][j] = cn;
            dh[(size_t)(t + 1) * pr::NN * pr::NN + idx] = cn;
            stable_acc += fabsf(cn - c);
        }
        __syncthreads();
    }

    if (tid >= 1 && tid < pr::NN) {
        const float* qrow = qh + (size_t)7 * pr::NN * pr::NN + tid * pr::NN;
        float s = 0.0f;
        for (int j = 0; j < pr::NN; j++) s += fabsf(qrow[j]);
        g_gf[b * pr::NG + (tid - 1)] = s;
    }

    float sp = 0.0f;
    for (int idx = tid; idx < pr::NG * pr::NG; idx += 512)
        sp += Cs[idx / pr::NG + 1][idx % pr::NG + 1];
    red[tid] = sp;
    __syncthreads();
    for (int o = 256; o > 0; o >>= 1) {
        if (tid < o) red[tid] += red[tid + o];
        __syncthreads();
    }
    if (tid == 0) g_aux_sp[b] = red[0];
    __syncthreads();
    red[tid] = stable_acc;
    __syncthreads();
    for (int o = 256; o > 0; o >>= 1) {
        if (tid < o) red[tid] += red[tid + o];
        __syncthreads();
    }
    if (tid == 0) g_aux_st[b] = red[0];
    __syncthreads();

    if (tid >= 1 && tid < pr::NN) {
        float rs = 0.0f;
        for (int j = 1; j < pr::NN; j++) rs += Cs[tid][j];
        degs[tid] = fmaxf(rs, 1e-6f);
    }
    __syncthreads();
    float* rout = out + pr::OFF_ROUT + (size_t)b * pr::NG * pr::NG;
    for (int idx = tid; idx < pr::NG * pr::NG; idx += 512) {
        const int i = idx / pr::NG + 1, j = idx % pr::NG + 1;
        rout[idx] = Cs[i][j] / degs[i];
    }
}

// ======================================================================
// K5: scores, exact top-k, masks, gid.
// ======================================================================
__global__ void __launch_bounds__(576) k_scores(const float* __restrict__ ls,
                                                const int* gh_p, const int* gw_p,
                                                float* __restrict__ out) {
    __shared__ float ts[pr::P];
    __shared__ float normg[pr::NG];
    __shared__ float sred[20];
    __shared__ float stats[4];

    const int b = blockIdx.x;
    const int tid = threadIdx.x;

    if (tid == 0) {
        float m = 0.0f;
        for (int g = 0; g < pr::NG; g++) m += g_gf[b * pr::NG + g];
        m /= (float)pr::NG;
        float v = 0.0f;
        for (int g = 0; g < pr::NG; g++) {
            const float d = g_gf[b * pr::NG + g] - m;
            v += d * d;
        }
        stats[0] = m;
        stats[1] = fmaxf(sqrtf(v / (float)(pr::NG - 1)), 1e-6f);
    }

    const float x = ls[(size_t)b * pr::P + tid];
    float s = x;
#pragma unroll
    for (int o = 16; o > 0; o >>= 1) s += __shfl_down_sync(0xffffffffu, s, o);
    if ((tid & 31) == 0) sred[tid >> 5] = s;
    __syncthreads();
    if (tid == 0) {
        float m = 0.0f;
        for (int w = 0; w < 18; w++) m += sred[w];
        stats[2] = m / (float)pr::P;
    }
    __syncthreads();
    const float dv = x - stats[2];
    float s2 = dv * dv;
#pragma unroll
    for (int o = 16; o > 0; o >>= 1) s2 += __shfl_down_sync(0xffffffffu, s2, o);
    if ((tid & 31) == 0) sred[tid >> 5] = s2;
    __syncthreads();
    if (tid == 0) {
        float v = 0.0f;
        for (int w = 0; w < 18; w++) v += sred[w];
        stats[3] = fmaxf(sqrtf(v / (float)(pr::P - 1)), 1e-6f);
    }
    if (tid < pr::NG)
        normg[tid] = (g_gf[b * pr::NG + tid] - stats[0]) / stats[1];
    __syncthreads();

    const int GH = gh_p ? *gh_p : 24;
    const int GW = gw_p ? *gw_p : 24;
    const int gh = (GH + 7) / 8, gw = (GW + 7) / 8;
    const int r = tid / GW, c = tid % GW;
    const int gidp = min(r / gh, 7) * 8 + min(c / gw, 7);

    const float gs = normg[gidp];
    const float myscore = gs + 0.5f * (x - stats[2]) / stats[3];
    ts[tid] = myscore;
    out[pr::OFF_GSC + b * pr::P + tid] = gs;
    out[pr::OFF_GID + b * pr::P + tid] = (float)gidp;
    __syncthreads();

    int cnt = 0;
    for (int q = 0; q < pr::P; q++) {
        const float tq = ts[q];
        cnt += (tq > myscore) || (tq == myscore && q < tid);
    }
    const float keep = (cnt < pr::KEEPC) ? 1.0f : 0.0f;
    out[pr::OFF_PATCH + b * pr::P + tid] = keep;
    out[pr::OFF_KEEP + b * (pr::P + 1) + 1 + tid] = keep;
    if (tid == 0) out[pr::OFF_KEEP + b * (pr::P + 1)] = 1.0f;
}

// ======================================================================
// K6: aux scalar finalization
// ======================================================================
__global__ void k_aux(float* __restrict__ out) {
    if (threadIdx.x == 0) {
        float s1 = 0.0f, s2 = 0.0f;
        for (int b = 0; b < pr::B; b++) {
            s1 += g_aux_sp[b];
            s2 += g_aux_st[b];
        }
        out[pr::OFF_SPARSE] = s1 / (float)pr::B;
        out[pr::OFF_STABLE] = s2 / (float)pr::B;
    }
}

// ======================================================================
extern "C" void kernel_launch(void* const* d_in, const int* in_sizes, int n_in,
                              void* d_out, int out_size) {
    const float* tokens = (const float*)d_in[0];
    const float* cls    = (const float*)d_in[1];
    const float* W      = (const float*)d_in[2];
    const float* ls     = (const float*)d_in[3];
    const int* ghp = (n_in > 4) ? (const int*)d_in[4] : nullptr;
    const int* gwp = (n_in > 5) ? (const int*)d_in[5] : nullptr;
    float* out = (float*)d_out;

    k_groups<<<pr::B * pr::NN, 256>>>(tokens, cls, ghp, gwp);

    dim3 gg(pr::D / 64, (pr::B * pr::NN + 127) / 128);   // 12 x 33
    k_gemm_tc<<<gg, 256>>>(W);

    k_gram_part<<<dim3(pr::B, pr::KCH), 256>>>();
    k_c0<<<pr::B, 256>>>(out);
    k_dyn<<<pr::B, 512>>>(out);
    k_scores<<<pr::B, pr::P>>>(ls, ghp, gwp, out);
    k_aux<<<1, 32>>>(out);
}